// round 1
// baseline (speedup 1.0000x reference)
#include <cuda_runtime.h>
#include <cstddef>

// Problem constants
#define BB 4
#define SS 2048
#define DD 1024
#define HH 16
#define DHH 64
#define MTOT (BB*SS)   // 8192

// Scratch (allocation-free rule: __device__ globals)
__device__ float g_qkv [BB*HH*SS*DHH];   // [b,h,s,dh]
__device__ float g_qkvT[BB*HH*DHH*SS];   // [b,h,dh,s]
__device__ float g_aout[MTOT*DD];        // [b*s, d]

// ---------------------------------------------------------------------------
// SGEMM: C[m,n] = sum_k A[m,k] * W[n,k]  (A row-major [M,1024], W row-major [N=1024,1024])
// MODE 0: A = x,        writes g_qkv (head-split) + g_qkvT (transposed)
// MODE 1: A = g_aout,   writes Cout[m*1024+n] + bias[n]
// Tiles: 128x128x32, 256 threads, 8x8 per thread.
// ---------------------------------------------------------------------------
template<int MODE>
__global__ __launch_bounds__(256, 2)
void gemm_kernel(const float* __restrict__ Ain,
                 const float* __restrict__ W,
                 const float* __restrict__ bias,
                 float* __restrict__ Cout)
{
    __shared__ float As[128*36];   // row-major [row][k], stride 36 (144B, 16B aligned)
    __shared__ float Bt[32*132];   // k-major  [k][n],  stride 132 (528B, 16B aligned)

    const float* A = (MODE == 0) ? Ain : g_aout;

    const int tid = threadIdx.x;
    const int tx  = tid & 15;      // 16 col-groups of 8
    const int ty  = tid >> 4;      // 16 row-groups of 8
    const int m0  = blockIdx.y * 128;
    const int n0  = blockIdx.x * 128;

    float acc[8][8];
    #pragma unroll
    for (int i = 0; i < 8; i++)
        #pragma unroll
        for (int j = 0; j < 8; j++) acc[i][j] = 0.f;

    const int ldr = tid >> 3;      // 0..31
    const int ldc = tid & 7;       // 0..7 (float4 index within 32-wide k tile)

    for (int kt = 0; kt < 32; kt++) {
        const int k0 = kt * 32;
        // Load A tile [128 x 32], keep row-major
        #pragma unroll
        for (int p = 0; p < 4; p++) {
            int r = p * 32 + ldr;
            float4 v = *(const float4*)&A[(size_t)(m0 + r) * 1024 + k0 + ldc * 4];
            *(float4*)&As[r * 36 + ldc * 4] = v;
        }
        // Load W tile [128 x 32], transpose to k-major
        #pragma unroll
        for (int p = 0; p < 4; p++) {
            int n = p * 32 + ldr;
            float4 v = *(const float4*)&W[(size_t)(n0 + n) * 1024 + k0 + ldc * 4];
            Bt[(ldc * 4 + 0) * 132 + n] = v.x;
            Bt[(ldc * 4 + 1) * 132 + n] = v.y;
            Bt[(ldc * 4 + 2) * 132 + n] = v.z;
            Bt[(ldc * 4 + 3) * 132 + n] = v.w;
        }
        __syncthreads();

        #pragma unroll 8
        for (int kk = 0; kk < 32; kk++) {
            float a[8];
            #pragma unroll
            for (int i = 0; i < 8; i++) a[i] = As[(ty * 8 + i) * 36 + kk];
            float4 b0 = *(float4*)&Bt[kk * 132 + tx * 8];
            float4 b1 = *(float4*)&Bt[kk * 132 + tx * 8 + 4];
            #pragma unroll
            for (int i = 0; i < 8; i++) {
                acc[i][0] += a[i] * b0.x;  acc[i][1] += a[i] * b0.y;
                acc[i][2] += a[i] * b0.z;  acc[i][3] += a[i] * b0.w;
                acc[i][4] += a[i] * b1.x;  acc[i][5] += a[i] * b1.y;
                acc[i][6] += a[i] * b1.z;  acc[i][7] += a[i] * b1.w;
            }
        }
        __syncthreads();
    }

    // Epilogue
    const int mb = m0 + ty * 8;
    const int nb = n0 + tx * 8;
    if (MODE == 0) {
        const int h_  = nb >> 6;        // 8 cols never cross a 64 boundary
        const int dh_ = nb & 63;
        #pragma unroll
        for (int i = 0; i < 8; i++) {
            int m = mb + i;
            int b_ = m >> 11;
            int s_ = m & 2047;
            float* dst = g_qkv + ((size_t)((b_ * 16 + h_) * 2048 + s_)) * 64 + dh_;
            float4 v0 = make_float4(acc[i][0], acc[i][1], acc[i][2], acc[i][3]);
            float4 v1 = make_float4(acc[i][4], acc[i][5], acc[i][6], acc[i][7]);
            *(float4*)(dst)     = v0;
            *(float4*)(dst + 4) = v1;
            // transposed copy for conflict-free K^T smem loads in attention
            #pragma unroll
            for (int j = 0; j < 8; j++)
                g_qkvT[((size_t)(b_ * 16 + h_) * 64 + dh_ + j) * 2048 + s_] = acc[i][j];
        }
    } else {
        float bv[8];
        #pragma unroll
        for (int j = 0; j < 8; j++) bv[j] = bias[nb + j];
        #pragma unroll
        for (int i = 0; i < 8; i++) {
            int m = mb + i;
            float4 v0 = make_float4(acc[i][0] + bv[0], acc[i][1] + bv[1],
                                    acc[i][2] + bv[2], acc[i][3] + bv[3]);
            float4 v1 = make_float4(acc[i][4] + bv[4], acc[i][5] + bv[5],
                                    acc[i][6] + bv[6], acc[i][7] + bv[7]);
            *(float4*)&Cout[(size_t)m * 1024 + nb]     = v0;
            *(float4*)&Cout[(size_t)m * 1024 + nb + 4] = v1;
        }
    }
}

// ---------------------------------------------------------------------------
// Flash attention, fp32. Per block: one (b,h) pair, 128 query rows.
// Loops over 32 key tiles of 64. Online softmax.
// Thread tile: 8 rows (ty) x 4 cols (tx). 256 threads.
// ---------------------------------------------------------------------------
#define ATTN_SMEM_FLOATS (8192 + 4352 + 4096 + 8704 + 2176 + 384)
#define ATTN_SMEM_BYTES  (ATTN_SMEM_FLOATS * 4)

__global__ __launch_bounds__(256, 2)
void attn_kernel()
{
    extern __shared__ float sm[];
    float* Qs   = sm;              // [128][64]
    float* Kt   = Qs + 8192;       // [64][68]   K transposed (d-major)
    float* Ks   = Kt + 4352;       // [64][64]   K/V natural (c-major)
    float* Ps   = Ks + 4096;       // [128][68]  softmax probs
    float* red  = Ps + 8704;       // [128][17]  row reductions
    float* mrow = red + 2176;      // [128]
    float* lrow = mrow + 128;      // [128]
    float* fac  = lrow + 128;      // [128]

    const int tid = threadIdx.x;
    const int tx  = tid & 15;
    const int ty  = tid >> 4;
    const int bh  = blockIdx.y;            // b*16 + h
    const int q0  = blockIdx.x * 128;

    const float* Qg  = g_qkv  + (size_t)bh * SS * DHH;
    const float* KTg = g_qkvT + (size_t)bh * DHH * SS;

    // Load Q tile [128 x 64]
    {
        int r0 = tid >> 4, c4 = tid & 15;
        #pragma unroll
        for (int p = 0; p < 8; p++) {
            int r = p * 16 + r0;
            *(float4*)&Qs[r * 64 + c4 * 4] =
                *(const float4*)&Qg[(size_t)(q0 + r) * 64 + c4 * 4];
        }
    }
    if (tid < 128) { mrow[tid] = -1e30f; lrow[tid] = 0.f; }

    float o[8][4];
    #pragma unroll
    for (int i = 0; i < 8; i++)
        #pragma unroll
        for (int j = 0; j < 4; j++) o[i][j] = 0.f;

    __syncthreads();

    for (int kt = 0; kt < 32; kt++) {
        const int c0 = kt * 64;
        // Load K^T tile: Kt[d][c] = K[c0+c][d]  (from g_qkvT, coalesced)
        {
            int r0 = tid >> 4, c4 = tid & 15;
            #pragma unroll
            for (int p = 0; p < 4; p++) {
                int dd = p * 16 + r0;
                *(float4*)&Kt[dd * 68 + c4 * 4] =
                    *(const float4*)&KTg[(size_t)dd * SS + c0 + c4 * 4];
            }
            // Load K/V natural: Ks[c][d]
            #pragma unroll
            for (int p = 0; p < 4; p++) {
                int cc = p * 16 + r0;
                *(float4*)&Ks[cc * 64 + c4 * 4] =
                    *(const float4*)&Qg[(size_t)(c0 + cc) * 64 + c4 * 4];
            }
        }
        __syncthreads();

        // S = Q K^T  (8x4 per thread)
        float sac[8][4];
        #pragma unroll
        for (int i = 0; i < 8; i++)
            #pragma unroll
            for (int j = 0; j < 4; j++) sac[i][j] = 0.f;

        #pragma unroll 4
        for (int d = 0; d < 64; d++) {
            float4 kb = *(float4*)&Kt[d * 68 + tx * 4];
            #pragma unroll
            for (int i = 0; i < 8; i++) {
                float q = Qs[(ty * 8 + i) * 64 + d];
                sac[i][0] += q * kb.x;  sac[i][1] += q * kb.y;
                sac[i][2] += q * kb.z;  sac[i][3] += q * kb.w;
            }
        }
        const float scale = 0.125f;   // 1/sqrt(64)
        #pragma unroll
        for (int i = 0; i < 8; i++)
            #pragma unroll
            for (int j = 0; j < 4; j++) sac[i][j] *= scale;

        // Row-max partials
        #pragma unroll
        for (int i = 0; i < 8; i++) {
            float tm = fmaxf(fmaxf(sac[i][0], sac[i][1]), fmaxf(sac[i][2], sac[i][3]));
            red[(ty * 8 + i) * 17 + tx] = tm;
        }
        __syncthreads();

        if (tid < 128) {
            float tm = red[tid * 17];
            #pragma unroll
            for (int t = 1; t < 16; t++) tm = fmaxf(tm, red[tid * 17 + t]);
            float mold = mrow[tid];
            float mnew = fmaxf(mold, tm);
            float f = __expf(mold - mnew);
            fac[tid]  = f;
            mrow[tid] = mnew;
            lrow[tid] *= f;
        }
        __syncthreads();

        // exp, partial row sums, rescale O
        #pragma unroll
        for (int i = 0; i < 8; i++) {
            int row = ty * 8 + i;
            float mn = mrow[row];
            float p0 = __expf(sac[i][0] - mn);
            float p1 = __expf(sac[i][1] - mn);
            float p2 = __expf(sac[i][2] - mn);
            float p3 = __expf(sac[i][3] - mn);
            *(float4*)&Ps[row * 68 + tx * 4] = make_float4(p0, p1, p2, p3);
            red[row * 17 + tx] = p0 + p1 + p2 + p3;
            float f = fac[row];
            o[i][0] *= f; o[i][1] *= f; o[i][2] *= f; o[i][3] *= f;
        }
        __syncthreads();

        if (tid < 128) {
            float s = 0.f;
            #pragma unroll
            for (int t = 0; t < 16; t++) s += red[tid * 17 + t];
            lrow[tid] += s;
        }

        // O += P V
        #pragma unroll 4
        for (int c = 0; c < 64; c++) {
            float4 vb = *(float4*)&Ks[c * 64 + tx * 4];
            #pragma unroll
            for (int i = 0; i < 8; i++) {
                float p = Ps[(ty * 8 + i) * 68 + c];
                o[i][0] += p * vb.x;  o[i][1] += p * vb.y;
                o[i][2] += p * vb.z;  o[i][3] += p * vb.w;
            }
        }
        __syncthreads();
    }

    // Epilogue: normalize and write to [b*s, d] layout for final GEMM
    const int b_ = bh >> 4;
    const int h_ = bh & 15;
    #pragma unroll
    for (int i = 0; i < 8; i++) {
        int row = ty * 8 + i;
        float inv = 1.f / lrow[row];
        float4 v = make_float4(o[i][0] * inv, o[i][1] * inv,
                               o[i][2] * inv, o[i][3] * inv);
        size_t idx = (size_t)(b_ * 2048 + q0 + row) * 1024 + h_ * 64 + tx * 4;
        *(float4*)&g_aout[idx] = v;
    }
}

// ---------------------------------------------------------------------------
extern "C" void kernel_launch(void* const* d_in, const int* in_sizes, int n_in,
                              void* d_out, int out_size)
{
    const float* x     = (const float*)d_in[0];
    const float* w_qkv = (const float*)d_in[1];
    const float* w_out = (const float*)d_in[2];
    const float* b_out = (const float*)d_in[3];
    float* out = (float*)d_out;

    cudaFuncSetAttribute(attn_kernel, cudaFuncAttributeMaxDynamicSharedMemorySize,
                         ATTN_SMEM_BYTES);

    dim3 gemm_grid(1024 / 128, MTOT / 128);   // (8, 64)
    gemm_kernel<0><<<gemm_grid, 256>>>(x, w_qkv, nullptr, nullptr);

    dim3 attn_grid(SS / 128, BB * HH);        // (16, 64)
    attn_kernel<<<attn_grid, 256, ATTN_SMEM_BYTES>>>();

    gemm_kernel<1><<<gemm_grid, 256>>>(nullptr, w_out, b_out, out);
}

// round 3
// speedup vs baseline: 3.1167x; 3.1167x over previous
#include <cuda_runtime.h>
#include <cstdint>
#include <cstddef>

// Problem constants
#define BB 4
#define SS 2048
#define DD 1024
#define HH 16
#define DHH 64
#define MTOT (BB*SS)   // 8192

// Scratch (allocation-free rule: __device__ globals)
__device__ float g_qkv [BB*HH*SS*DHH];   // [b,h,s,dh]  (tf32-rounded)
__device__ float g_qkvT[BB*HH*DHH*SS];   // [b,h,dh,s]  (tf32-rounded)
__device__ float g_aout[MTOT*DD];        // [b*s, d]    (tf32-rounded)

// ---------------------------------------------------------------------------
// Helpers
// ---------------------------------------------------------------------------
__device__ __forceinline__ uint32_t smem_u32(const void* p) {
    uint32_t a;
    asm("{ .reg .u64 t; cvta.to.shared.u64 t, %1; cvt.u32.u64 %0, t; }"
        : "=r"(a) : "l"(p));
    return a;
}
__device__ __forceinline__ void cp16(uint32_t s, const void* g) {
    asm volatile("cp.async.cg.shared.global [%0], [%1], 16;" :: "r"(s), "l"(g));
}
#define CP_COMMIT() asm volatile("cp.async.commit_group;" ::: "memory")
#define CP_WAIT(n)  asm volatile("cp.async.wait_group %0;" :: "n"(n) : "memory")

// round fp32 -> tf32 (round to nearest) returning bits
__device__ __forceinline__ uint32_t f2tf(float f) {
    uint32_t u;
    asm("cvt.rna.tf32.f32 %0, %1;" : "=r"(u) : "f"(f));
    return u;
}
__device__ __forceinline__ float tf_f(float f) { return __uint_as_float(f2tf(f)); }

// D += A * B   (m16n8k8, tf32 in, fp32 accumulate)
__device__ __forceinline__ void mma8(float* c, const uint32_t* a,
                                     uint32_t b0, uint32_t b1) {
    asm volatile(
        "mma.sync.aligned.m16n8k8.row.col.f32.tf32.tf32.f32 "
        "{%0,%1,%2,%3}, {%4,%5,%6,%7}, {%8,%9}, {%0,%1,%2,%3};\n"
        : "+f"(c[0]), "+f"(c[1]), "+f"(c[2]), "+f"(c[3])
        : "r"(a[0]), "r"(a[1]), "r"(a[2]), "r"(a[3]), "r"(b0), "r"(b1));
}

// ---------------------------------------------------------------------------
// tf32 GEMM: C[m,n] = sum_k A[m,k] * W[n,k]
// CTA 128x128, k-tile 32, 256 threads = 8 warps of 32m x 64n.
// smem rows padded to stride 36 floats -> all fragment LDS conflict-free.
// MODE 0: A=x -> g_qkv (tf32-rounded) + g_qkvT.  MODE 1: A=g_aout -> out+bias.
// ---------------------------------------------------------------------------
#define GEMM_SMEM_BYTES (4 * 9216 * 4)   // As[2][4608] + Bs[2][4608] floats

template<int MODE>
__global__ __launch_bounds__(256, 1)
void tgemm(const float* __restrict__ Ain, const float* __restrict__ W,
           const float* __restrict__ bias, float* __restrict__ Cout)
{
    extern __shared__ float sg[];
    float* As = sg;            // [2][128][36]
    float* Bs = sg + 9216;     // [2][128][36]

    const int tid = threadIdx.x;
    const int wid = tid >> 5, l = tid & 31;
    const int gy = l >> 2, gx = l & 3;
    const int wm = wid >> 1, wn = wid & 1;
    const int m0 = blockIdx.y * 128, n0 = blockIdx.x * 128;
    const float* A = (MODE == 0) ? Ain : g_aout;

    float acc[16][4];
    #pragma unroll
    for (int i = 0; i < 16; i++)
        #pragma unroll
        for (int j = 0; j < 4; j++) acc[i][j] = 0.f;

    float4 ra[4], rb[4];
    const int ch_row[4] = { (0*256+tid) >> 3, (1*256+tid) >> 3,
                            (2*256+tid) >> 3, (3*256+tid) >> 3 };
    const int ch_c4 = tid & 7;

    auto ldg = [&](int kt) {
        const int k0 = kt * 32;
        #pragma unroll
        for (int p = 0; p < 4; p++) {
            ra[p] = *(const float4*)&A[(size_t)(m0 + ch_row[p]) * 1024 + k0 + ch_c4 * 4];
            rb[p] = *(const float4*)&W[(size_t)(n0 + ch_row[p]) * 1024 + k0 + ch_c4 * 4];
        }
    };
    auto sts = [&](int st) {
        #pragma unroll
        for (int p = 0; p < 4; p++) {
            float4 va = make_float4(tf_f(ra[p].x), tf_f(ra[p].y),
                                    tf_f(ra[p].z), tf_f(ra[p].w));
            float4 vb = make_float4(tf_f(rb[p].x), tf_f(rb[p].y),
                                    tf_f(rb[p].z), tf_f(rb[p].w));
            *(float4*)&As[st * 4608 + ch_row[p] * 36 + ch_c4 * 4] = va;
            *(float4*)&Bs[st * 4608 + ch_row[p] * 36 + ch_c4 * 4] = vb;
        }
    };
    auto compute = [&](int st) {
        const float* as = As + st * 4608;
        const float* bs = Bs + st * 4608;
        #pragma unroll
        for (int k8 = 0; k8 < 4; k8++) {
            const int kk = k8 * 8 + gx;
            uint32_t a[2][4];
            #pragma unroll
            for (int fm = 0; fm < 2; fm++) {
                const int r = wm * 32 + fm * 16 + gy;
                a[fm][0] = __float_as_uint(as[r * 36 + kk]);
                a[fm][1] = __float_as_uint(as[(r + 8) * 36 + kk]);
                a[fm][2] = __float_as_uint(as[r * 36 + kk + 4]);
                a[fm][3] = __float_as_uint(as[(r + 8) * 36 + kk + 4]);
            }
            #pragma unroll
            for (int fn = 0; fn < 8; fn++) {
                const int rn = wn * 64 + fn * 8 + gy;
                uint32_t b0 = __float_as_uint(bs[rn * 36 + kk]);
                uint32_t b1 = __float_as_uint(bs[rn * 36 + kk + 4]);
                mma8(acc[fn],     a[0], b0, b1);
                mma8(acc[8 + fn], a[1], b0, b1);
            }
        }
    };

    ldg(0); sts(0);
    __syncthreads();
    for (int kt = 0; kt < 32; kt++) {
        const int st = kt & 1;
        if (kt < 31) ldg(kt + 1);
        compute(st);
        __syncthreads();
        if (kt < 31) sts(st ^ 1);
        __syncthreads();
    }

    // Epilogue
    #pragma unroll
    for (int fm = 0; fm < 2; fm++) {
        const int mrow = m0 + wm * 32 + fm * 16 + gy;
        #pragma unroll
        for (int fn = 0; fn < 8; fn++) {
            const float* cc = acc[fm * 8 + fn];
            const int n = n0 + wn * 64 + fn * 8 + 2 * gx;
            if (MODE == 0) {
                float v0 = tf_f(cc[0]), v1 = tf_f(cc[1]);
                float v2 = tf_f(cc[2]), v3 = tf_f(cc[3]);
                const int h_ = n >> 6, dh = n & 63;
                const int b_ = mrow >> 11, s_ = mrow & 2047;
                float* d0 = g_qkv + ((size_t)(b_ * 16 + h_) * 2048 + s_) * 64 + dh;
                *(float2*)d0 = make_float2(v0, v1);
                *(float2*)(d0 + 8 * 64) = make_float2(v2, v3);
                float* t0 = g_qkvT + ((size_t)(b_ * 16 + h_) * 64 + dh) * 2048 + s_;
                t0[0] = v0;  t0[2048] = v1;
                t0[8]  = v2; t0[2048 + 8] = v3;
            } else {
                float2 bv = *(const float2*)&bias[n];
                *(float2*)&Cout[(size_t)mrow * 1024 + n] =
                    make_float2(cc[0] + bv.x, cc[1] + bv.y);
                *(float2*)&Cout[(size_t)(mrow + 8) * 1024 + n] =
                    make_float2(cc[2] + bv.x, cc[3] + bv.y);
            }
        }
    }
}

// ---------------------------------------------------------------------------
// Flash attention on mma.sync tf32.
// CTA: 256 thr = 8 warps, each warp owns 16 q rows. kc-tile = 64.
// Q fragments cached in registers; K/V^T tiles double-buffered via cp.async.
// Softmax row stats via shfl.bfly; P->A-fragment permutation via shfl.
// ---------------------------------------------------------------------------
#define ATTN_SMEM_BYTES (4 * 4352 * 4)   // Ks[2][64][68] + Vt[2][64][68]

__global__ __launch_bounds__(256, 1)
void attn_kernel()
{
    extern __shared__ float sm[];        // Ks: [0,8704), Vt: [8704,17408) floats
    const uint32_t sbase = smem_u32(sm);

    const int tid = threadIdx.x;
    const int wid = tid >> 5, l = tid & 31;
    const int gy = l >> 2, gx = l & 3;
    const int bh = blockIdx.y;
    const int q0 = blockIdx.x * 128;

    const float* Kg0 = g_qkv  + (size_t)bh * SS * DHH;
    const float* Vg0 = g_qkvT + (size_t)bh * DHH * SS;

    // Cache Q fragments (16 rows starting at q0 + 16*wid); already tf32-rounded.
    uint32_t qf[8][4];
    {
        const float* Qg = Kg0 + (size_t)(q0 + wid * 16) * 64;
        #pragma unroll
        for (int s = 0; s < 8; s++) {
            qf[s][0] = __float_as_uint(Qg[gy * 64 + s * 8 + gx]);
            qf[s][1] = __float_as_uint(Qg[(gy + 8) * 64 + s * 8 + gx]);
            qf[s][2] = __float_as_uint(Qg[gy * 64 + s * 8 + gx + 4]);
            qf[s][3] = __float_as_uint(Qg[(gy + 8) * 64 + s * 8 + gx + 4]);
        }
    }

    float o[8][4];
    #pragma unroll
    for (int i = 0; i < 8; i++)
        #pragma unroll
        for (int j = 0; j < 4; j++) o[i][j] = 0.f;
    float m0 = -1e30f, m1 = -1e30f, l0 = 0.f, l1 = 0.f;

    // stage kc-tile ct into buffer st
    auto stage_kv = [&](int ct, int st) {
        const float* Kg = Kg0 + (size_t)(ct * 64) * 64;
        const float* Vg = Vg0 + ct * 64;
        const uint32_t kd = sbase + st * 17408;
        const uint32_t vd = sbase + 34816 + st * 17408;
        #pragma unroll
        for (int p = 0; p < 4; p++) {
            int c = p * 256 + tid;          // 1024 chunks of 16B
            int row = c >> 4, c4 = c & 15;
            cp16(kd + row * 272 + c4 * 16, Kg + row * 64 + c4 * 4);
            cp16(vd + row * 272 + c4 * 16, Vg + (size_t)row * SS + c4 * 4);
        }
        CP_COMMIT();
    };

    stage_kv(0, 0);

    for (int ct = 0; ct < 32; ct++) {
        const int st = ct & 1;
        if (ct + 1 < 32) { stage_kv(ct + 1, st ^ 1); CP_WAIT(1); }
        else             { CP_WAIT(0); }
        __syncthreads();

        const float* ks = sm + st * 4352;
        const float* vt = sm + 8704 + st * 4352;

        // ---- S = Q K^T (scaled) ----
        float sc[8][4];
        #pragma unroll
        for (int j = 0; j < 8; j++)
            #pragma unroll
            for (int v = 0; v < 4; v++) sc[j][v] = 0.f;

        #pragma unroll
        for (int s = 0; s < 8; s++) {
            #pragma unroll
            for (int j = 0; j < 8; j++) {
                uint32_t b0 = __float_as_uint(ks[(j * 8 + gy) * 68 + s * 8 + gx]);
                uint32_t b1 = __float_as_uint(ks[(j * 8 + gy) * 68 + s * 8 + gx + 4]);
                mma8(sc[j], qf[s], b0, b1);
            }
        }
        #pragma unroll
        for (int j = 0; j < 8; j++)
            #pragma unroll
            for (int v = 0; v < 4; v++) sc[j][v] *= 0.125f;

        // ---- online softmax (rows gy and gy+8, owned by 4-lane groups) ----
        float mx0 = -1e30f, mx1 = -1e30f;
        #pragma unroll
        for (int j = 0; j < 8; j++) {
            mx0 = fmaxf(mx0, fmaxf(sc[j][0], sc[j][1]));
            mx1 = fmaxf(mx1, fmaxf(sc[j][2], sc[j][3]));
        }
        mx0 = fmaxf(mx0, __shfl_xor_sync(0xffffffffu, mx0, 1));
        mx0 = fmaxf(mx0, __shfl_xor_sync(0xffffffffu, mx0, 2));
        mx1 = fmaxf(mx1, __shfl_xor_sync(0xffffffffu, mx1, 1));
        mx1 = fmaxf(mx1, __shfl_xor_sync(0xffffffffu, mx1, 2));

        float mn0 = fmaxf(m0, mx0), mn1 = fmaxf(m1, mx1);
        float f0 = __expf(m0 - mn0), f1 = __expf(m1 - mn1);
        m0 = mn0; m1 = mn1;
        l0 *= f0;  l1 *= f1;

        uint32_t pt[8][4];
        float s0 = 0.f, s1 = 0.f;
        #pragma unroll
        for (int j = 0; j < 8; j++) {
            float p0 = __expf(sc[j][0] - m0);
            float p1 = __expf(sc[j][1] - m0);
            float p2 = __expf(sc[j][2] - m1);
            float p3 = __expf(sc[j][3] - m1);
            s0 += p0 + p1;  s1 += p2 + p3;
            pt[j][0] = f2tf(p0); pt[j][1] = f2tf(p1);
            pt[j][2] = f2tf(p2); pt[j][3] = f2tf(p3);
        }
        s0 += __shfl_xor_sync(0xffffffffu, s0, 1);
        s0 += __shfl_xor_sync(0xffffffffu, s0, 2);
        s1 += __shfl_xor_sync(0xffffffffu, s1, 1);
        s1 += __shfl_xor_sync(0xffffffffu, s1, 2);
        l0 += s0;  l1 += s1;

        #pragma unroll
        for (int jd = 0; jd < 8; jd++) {
            o[jd][0] *= f0; o[jd][1] *= f0;
            o[jd][2] *= f1; o[jd][3] *= f1;
        }

        // ---- O += P V : A-frags of P via shuffle, B-frags from Vt ----
        #pragma unroll
        for (int g = 0; g < 8; g++) {
            const int src = (l & ~3) | (gx >> 1);
            uint32_t u0 = __shfl_sync(0xffffffffu, pt[g][0], src);
            uint32_t u1 = __shfl_sync(0xffffffffu, pt[g][1], src);
            uint32_t u2 = __shfl_sync(0xffffffffu, pt[g][2], src);
            uint32_t u3 = __shfl_sync(0xffffffffu, pt[g][3], src);
            uint32_t w0 = __shfl_sync(0xffffffffu, pt[g][0], src + 2);
            uint32_t w1 = __shfl_sync(0xffffffffu, pt[g][1], src + 2);
            uint32_t w2 = __shfl_sync(0xffffffffu, pt[g][2], src + 2);
            uint32_t w3 = __shfl_sync(0xffffffffu, pt[g][3], src + 2);
            uint32_t a[4];
            a[0] = (l & 1) ? u1 : u0;
            a[1] = (l & 1) ? u3 : u2;
            a[2] = (l & 1) ? w1 : w0;
            a[3] = (l & 1) ? w3 : w2;
            #pragma unroll
            for (int jd = 0; jd < 8; jd++) {
                uint32_t b0 = __float_as_uint(vt[(jd * 8 + gy) * 68 + g * 8 + gx]);
                uint32_t b1 = __float_as_uint(vt[(jd * 8 + gy) * 68 + g * 8 + gx + 4]);
                mma8(o[jd], a, b0, b1);
            }
        }
        __syncthreads();
    }

    // Epilogue -> g_aout [b*s, h*64+d], tf32-rounded for GEMM2
    const float inv0 = 1.f / l0, inv1 = 1.f / l1;
    const int b_ = bh >> 4, h_ = bh & 15;
    const int r0 = q0 + wid * 16 + gy;
    float* out0 = g_aout + (size_t)(b_ * 2048 + r0) * 1024 + h_ * 64;
    float* out1 = out0 + (size_t)8 * 1024;
    #pragma unroll
    for (int jd = 0; jd < 8; jd++) {
        const int d = jd * 8 + 2 * gx;
        *(float2*)(out0 + d) = make_float2(tf_f(o[jd][0] * inv0),
                                           tf_f(o[jd][1] * inv0));
        *(float2*)(out1 + d) = make_float2(tf_f(o[jd][2] * inv1),
                                           tf_f(o[jd][3] * inv1));
    }
}

// ---------------------------------------------------------------------------
extern "C" void kernel_launch(void* const* d_in, const int* in_sizes, int n_in,
                              void* d_out, int out_size)
{
    const float* x     = (const float*)d_in[0];
    const float* w_qkv = (const float*)d_in[1];
    const float* w_out = (const float*)d_in[2];
    const float* b_out = (const float*)d_in[3];
    float* out = (float*)d_out;

    cudaFuncSetAttribute(tgemm<0>, cudaFuncAttributeMaxDynamicSharedMemorySize,
                         GEMM_SMEM_BYTES);
    cudaFuncSetAttribute(tgemm<1>, cudaFuncAttributeMaxDynamicSharedMemorySize,
                         GEMM_SMEM_BYTES);
    cudaFuncSetAttribute(attn_kernel, cudaFuncAttributeMaxDynamicSharedMemorySize,
                         ATTN_SMEM_BYTES);

    dim3 gemm_grid(1024 / 128, MTOT / 128);   // (8, 64)
    tgemm<0><<<gemm_grid, 256, GEMM_SMEM_BYTES>>>(x, w_qkv, nullptr, nullptr);

    dim3 attn_grid(SS / 128, BB * HH);        // (16, 64)
    attn_kernel<<<attn_grid, 256, ATTN_SMEM_BYTES>>>();

    tgemm<1><<<gemm_grid, 256, GEMM_SMEM_BYTES>>>(nullptr, w_out, b_out, out);
}